// round 16
// baseline (speedup 1.0000x reference)
#include <cuda_runtime.h>
#include <cuda_fp16.h>
#include <cstdint>

#define HIDDEN    2048
#define INTER     5504
#define INTER_PAD 5632            /* 22 * 256 */
#define NFUSED    (2 * INTER_PAD) /* gate cols 0..5631, up cols 5632..11263 */
#define TSTEPS    4
#define MROWS     4096            /* T*BSZ*SEQ */
#define BSROWS    1024            /* BSZ*SEQ */

#define KTILE     64              /* fp16 K-elements per tile: 128B rows */
#define BUF_BYTES 49152           /* A 16KB + B 32KB */
#define DYN_SMEM  (2 * BUF_BYTES)

// ---------------- scratch (device globals; no allocation allowed) ----------
__device__ __half g_X  [(size_t)MROWS * HIDDEN];
__device__ __half g_WGU[(size_t)NFUSED * HIDDEN];   /* rows 0..5631 gate, 5632.. up */
__device__ __half g_WD [(size_t)HIDDEN * INTER_PAD];
__device__ __half g_GU [(size_t)MROWS * NFUSED];    /* fused gate/up outputs, fp16 */
__device__ __half g_C  [(size_t)MROWS * INTER_PAD]; /* combine output, fp16 */

// ---------------- helpers ----------------------------------------------------
__device__ __forceinline__ uint32_t smem_u32(const void* p) {
    uint32_t a;
    asm("{ .reg .u64 t; cvta.to.shared.u64 t, %1; cvt.u32.u64 %0, t; }" : "=r"(a) : "l"(p));
    return a;
}

#define LDSM_X4(r0, r1, r2, r3, addr) \
    asm volatile("ldmatrix.sync.aligned.m8n8.x4.shared.b16 {%0,%1,%2,%3}, [%4];" \
                 : "=r"(r0), "=r"(r1), "=r"(r2), "=r"(r3) : "r"(addr))

__device__ __forceinline__ void mma_f16(float* d, const uint32_t* a, const uint32_t* b) {
    asm volatile(
        "mma.sync.aligned.m16n8k16.row.col.f32.f16.f16.f32 "
        "{%0,%1,%2,%3}, {%4,%5,%6,%7}, {%8,%9}, {%0,%1,%2,%3};\n"
        : "+f"(d[0]), "+f"(d[1]), "+f"(d[2]), "+f"(d[3])
        : "r"(a[0]), "r"(a[1]), "r"(a[2]), "r"(a[3]), "r"(b[0]), "r"(b[1]));
}

// ---------------- GEMM: C[m,n] = sum_k A[m,k]*B[n,k] ------------------------
// Block tile 128x256, 256 threads, 8 warps (2x4), warp tile 64x64.
// Register-prefetched globals, double-buffered smem, one barrier per K-tile,
// LDSM fragment loads INTERLEAVED into the MMA stream (volatile-asm order is
// preserved by ptxas, so this is a real schedule change), m16n8k16 fp16 MMA,
// fp32 accumulation. OutT = __half or float. M%128==0, N%256==0, K%64==0.
template <typename OutT>
__global__ void __launch_bounds__(256, 1)
gemm_tn(const __half* __restrict__ A, const __half* __restrict__ B,
        OutT* __restrict__ C, int K, int N)
{
    extern __shared__ __align__(16) uint8_t smraw[];
    uint4* sm = reinterpret_cast<uint4*>(smraw);
    const uint32_t sb = smem_u32(smraw);

    const int tid  = threadIdx.x;
    const int lane = tid & 31;
    const int warp = tid >> 5;
    const int wm   = warp & 1;   // 2 warp rows of 64
    const int wn   = warp >> 1;  // 4 warp cols of 64

    const int r = tid >> 3;      // 0..31 : row within group of 32
    const int c = tid & 7;       // 0..7  : 16B (k8) atom within 128B row

    // LDSM per-lane selectors (verified bit-exact since R4):
    const int rsel   = lane & 7;
    const int a_k8hi = lane >> 4;
    const int a_moff = ((lane >> 3) & 1) << 3;
    const int b_k8lo = (lane >> 3) & 1;
    const int b_noff = (lane >> 4) << 3;
    const int mrowA  = wm * 64 + a_moff + rsel;
    const int nrowB  = wn * 64 + b_noff + rsel;

    const size_t mBase = (size_t)blockIdx.y * 128;
    const size_t nBase = (size_t)blockIdx.x * 256;
    const int NK = K / KTILE;

    const __half* Ag = A + (mBase + (size_t)r) * (size_t)K + (size_t)c * 8;
    const __half* Bg = B + (nBase + (size_t)r) * (size_t)K + (size_t)c * 8;

    uint4 pa[4], pb[8];

    auto ldg_tile = [&](int kt) {
        const __half* Ak = Ag + (size_t)kt * KTILE;
        const __half* Bk = Bg + (size_t)kt * KTILE;
        #pragma unroll
        for (int j = 0; j < 4; ++j)
            pa[j] = *(const uint4*)(Ak + (size_t)(j * 32) * K);
        #pragma unroll
        for (int j = 0; j < 8; ++j)
            pb[j] = *(const uint4*)(Bk + (size_t)(j * 32) * K);
    };
    auto sts_tile = [&](int buf) {
        uint4* As = sm + buf * (BUF_BYTES / 16);
        uint4* Bs = As + 1024;
        #pragma unroll
        for (int j = 0; j < 4; ++j) {
            const int m = j * 32 + r;
            As[c * 128 + (m ^ c)] = pa[j];
        }
        #pragma unroll
        for (int j = 0; j < 8; ++j) {
            const int n = j * 32 + r;
            Bs[c * 256 + (n ^ c)] = pb[j];
        }
    };

    float acc[4][8][4];
    #pragma unroll
    for (int i = 0; i < 4; ++i)
        #pragma unroll
        for (int j = 0; j < 8; ++j)
            #pragma unroll
            for (int q = 0; q < 4; ++q) acc[i][j][q] = 0.f;

    // prologue
    ldg_tile(0);
    sts_tile(0);
    if (NK > 1) ldg_tile(1);
    __syncthreads();

    for (int kt = 0; kt < NK; ++kt) {
        if (kt + 1 < NK) {
            sts_tile((kt + 1) & 1);
            if (kt + 2 < NK) ldg_tile(kt + 2);
        }

        const uint32_t abase = sb + (uint32_t)((kt & 1) * BUF_BYTES);
        const uint32_t bbase = abase + 16384;

        #pragma unroll
        for (int ks = 0; ks < 4; ++ks) {        // 4 k16-steps over 64-K tile
            const uint32_t ak8 = (uint32_t)(ks * 2 + a_k8hi);
            const uint32_t bk8 = (uint32_t)(ks * 2 + b_k8lo);

            // A fragments for this k16-step (4 LDSM; covered by prior MMA tail)
            uint32_t af[4][4];
            #pragma unroll
            for (int im = 0; im < 4; ++im) {
                const uint32_t m = (uint32_t)(mrowA + im * 16);
                const uint32_t addr = abase + (ak8 << 11) + (((m ^ ak8) & 127u) << 4);
                LDSM_X4(af[im][0], af[im][1], af[im][2], af[im][3], addr);
            }
            // B: one LDSM.x4 (2 jn-pairs) immediately followed by its 8 MMAs —
            // each LDSM is latency-covered by the preceding MMA group.
            #pragma unroll
            for (int p = 0; p < 4; ++p) {
                uint32_t bp[4];
                const uint32_t n = (uint32_t)(nrowB + p * 16);
                const uint32_t addr = bbase + (bk8 << 12) + (((n ^ bk8) & 255u) << 4);
                LDSM_X4(bp[0], bp[1], bp[2], bp[3], addr);
                #pragma unroll
                for (int im = 0; im < 4; ++im) {
                    mma_f16(acc[im][2 * p],     af[im], bp);
                    mma_f16(acc[im][2 * p + 1], af[im], bp + 2);
                }
            }
        }
        __syncthreads();
    }

    // Epilogue: fragment layout -> global (pair of cols per quad-lane).
    const int g  = lane >> 2;
    const int q2 = (lane & 3) * 2;
    #pragma unroll
    for (int im = 0; im < 4; ++im) {
        const size_t row0 = mBase + wm * 64 + im * 16 + g;
        #pragma unroll
        for (int jn = 0; jn < 8; ++jn) {
            const size_t col0 = nBase + wn * 64 + jn * 8 + q2;
            if constexpr (sizeof(OutT) == 4) {
                *(float2*)&C[row0 * (size_t)N + col0] =
                    make_float2(acc[im][jn][0], acc[im][jn][1]);
                *(float2*)&C[(row0 + 8) * (size_t)N + col0] =
                    make_float2(acc[im][jn][2], acc[im][jn][3]);
            } else {
                *(__half2*)&C[row0 * (size_t)N + col0] =
                    __floats2half2_rn(acc[im][jn][0], acc[im][jn][1]);
                *(__half2*)&C[(row0 + 8) * (size_t)N + col0] =
                    __floats2half2_rn(acc[im][jn][2], acc[im][jn][3]);
            }
        }
    }
}

// ---------------- fused prepass (one launch) --------------------------------
__device__ __forceinline__ void store_h4(__half* dst, float4 v) {
    __half2* d2 = reinterpret_cast<__half2*>(dst);
    d2[0] = __floats2half2_rn(v.x, v.y);
    d2[1] = __floats2half2_rn(v.z, v.w);
}

#define PREP_S1 ((long)MROWS * HIDDEN / 4)               /* x copy          */
#define PREP_S2 (PREP_S1 + (long)INTER_PAD * HIDDEN / 4) /* gate (pad rows) */
#define PREP_S3 (PREP_S2 + (long)INTER_PAD * HIDDEN / 4) /* up   (pad rows) */
#define PREP_S4 (PREP_S3 + (long)HIDDEN * INTER_PAD / 4) /* w_down pad cols */

__global__ void prep_k(const float* __restrict__ x,
                       const float* __restrict__ wg, const float* __restrict__ wu,
                       const float* __restrict__ wd,
                       __half* __restrict__ dX, __half* __restrict__ dWGU,
                       __half* __restrict__ dWD)
{
    long i = (long)blockIdx.x * blockDim.x + threadIdx.x;
    if (i < PREP_S1) {
        long e = i * 4;
        store_h4(dX + e, *(const float4*)(x + e));
    } else if (i < PREP_S3) {
        const bool isUp = (i >= PREP_S2);
        long e = (i - (isUp ? PREP_S2 : PREP_S1)) * 4;
        int row = (int)(e / HIDDEN);
        float4 v = make_float4(0.f, 0.f, 0.f, 0.f);
        if (row < INTER) {
            const float* src = isUp ? wu : wg;
            v = *(const float4*)(src + (size_t)row * HIDDEN + (e % HIDDEN));
        }
        store_h4(dWGU + (isUp ? (size_t)INTER_PAD * HIDDEN : 0) + e, v);
    } else if (i < PREP_S4) {
        long e = (i - PREP_S3) * 4;
        int row = (int)(e / INTER_PAD);
        int col = (int)(e % INTER_PAD);
        float4 v = make_float4(0.f, 0.f, 0.f, 0.f);
        if (col < INTER)
            v = *(const float4*)(wd + (size_t)row * INTER + col);
        store_h4(dWD + e, v);
    }
}

// ---------------- combine: vectorized (8 cols per thread) -------------------
#define CCOL8 (INTER_PAD / 8)   /* 704 uint4 chunks per row */

__device__ __forceinline__ void h8_to_f(const uint4 q, float* f) {
    const __half2* h2 = reinterpret_cast<const __half2*>(&q);
    #pragma unroll
    for (int j = 0; j < 4; ++j) {
        float2 v = __half22float2(h2[j]);
        f[2 * j] = v.x; f[2 * j + 1] = v.y;
    }
}

__global__ void combine_k()
{
    const long total8 = (long)BSROWS * CCOL8;
    long idx = (long)blockIdx.x * blockDim.x + threadIdx.x;
    if (idx >= total8) return;

    const int row  = (int)(idx / CCOL8);
    const int col  = (int)(idx % CCOL8) * 8;
    const size_t rstride = (size_t)BSROWS * NFUSED;     // t-slab stride in GU
    const size_t cstride = (size_t)BSROWS * INTER_PAD;  // t-slab stride in C

    float gv[TSTEPS][8], uv[TSTEPS][8];
    #pragma unroll
    for (int t = 0; t < TSTEPS; ++t) {
        const __half* base = g_GU + (size_t)t * rstride + (size_t)row * NFUSED;
        h8_to_f(*(const uint4*)(base + col),             gv[t]);
        h8_to_f(*(const uint4*)(base + INTER_PAD + col), uv[t]);
    }

    float outv[TSTEPS][8];
    #pragma unroll
    for (int j = 0; j < 8; ++j) {
        float X = 0.f, Yprev = 0.f, SB = 0.f;
        float Av[TSTEPS];
        #pragma unroll
        for (int t = 0; t < TSTEPS; ++t) {
            X += gv[t][j];
            const float Y = X / (1.f + expf(-X));   // silu of cumsum
            Av[t] = Y - Yprev;
            Yprev = Y;
            SB += uv[t][j];
        }
        const float SA = Yprev;                     // telescoping sum of A
        #pragma unroll
        for (int t = 0; t < TSTEPS; ++t)
            outv[t][j] = 0.5f * (Av[t] * SB + uv[t][j] * SA);
    }

    #pragma unroll
    for (int t = 0; t < TSTEPS; ++t) {
        uint4 q;
        __half2* h2 = reinterpret_cast<__half2*>(&q);
        #pragma unroll
        for (int j = 0; j < 4; ++j)
            h2[j] = __floats2half2_rn(outv[t][2 * j], outv[t][2 * j + 1]);
        *(uint4*)(g_C + (size_t)t * cstride + (size_t)row * INTER_PAD + col) = q;
    }
}

// ---------------- launch -----------------------------------------------------
extern "C" void kernel_launch(void* const* d_in, const int* in_sizes, int n_in,
                              void* d_out, int out_size)
{
    const float* x      = (const float*)d_in[0];
    const float* w_gate = (const float*)d_in[1];
    const float* w_up   = (const float*)d_in[2];
    const float* w_down = (const float*)d_in[3];
    float* out = (float*)d_out;
    (void)in_sizes; (void)n_in; (void)out_size;

    __half *dX, *dWGU, *dWD, *dGU, *dC;
    cudaGetSymbolAddress((void**)&dX,   g_X);
    cudaGetSymbolAddress((void**)&dWGU, g_WGU);
    cudaGetSymbolAddress((void**)&dWD,  g_WD);
    cudaGetSymbolAddress((void**)&dGU,  g_GU);
    cudaGetSymbolAddress((void**)&dC,   g_C);

    cudaFuncSetAttribute(gemm_tn<__half>, cudaFuncAttributeMaxDynamicSharedMemorySize, DYN_SMEM);
    cudaFuncSetAttribute(gemm_tn<float>,  cudaFuncAttributeMaxDynamicSharedMemorySize, DYN_SMEM);

    // Fused prepass (one launch): fp32 -> fp16, weight pad/concat.
    prep_k<<<(unsigned)((PREP_S4 + 255) / 256), 256>>>(x, w_gate, w_up, w_down,
                                                       dX, dWGU, dWD);

    // Fused gate+up projection: (4096 x 11264) = x(4096x2048) @ [WG;WU]^T -> fp16
    {
        dim3 grid(NFUSED / 256, MROWS / 128);      // 44 x 32
        gemm_tn<__half><<<grid, 256, DYN_SMEM>>>(dX, dWGU, dGU, HIDDEN, NFUSED);
    }

    // Combine (vectorized: 8 cols/thread, fp32 math, fp16 out).
    {
        long total8 = (long)BSROWS * CCOL8;
        combine_k<<<(unsigned)((total8 + 255) / 256), 256>>>();
    }

    // Down projection: (4096 x 2048) = C(4096x5632) @ w_down'^T -> fp32 out
    {
        dim3 grid(HIDDEN / 256, MROWS / 128);      // 8 x 32
        gemm_tn<float><<<grid, 256, DYN_SMEM>>>(dC, dWD, out, INTER_PAD, HIDDEN);
    }
}

// round 17
// speedup vs baseline: 1.0658x; 1.0658x over previous
#include <cuda_runtime.h>
#include <cuda_fp16.h>
#include <cstdint>

#define HIDDEN    2048
#define INTER     5504
#define INTER_PAD 5632            /* 22 * 256, 44 * 128 */
#define NFUSED    (2 * INTER_PAD) /* gate cols 0..5631, up cols 5632..11263 */
#define TSTEPS    4
#define MROWS     4096            /* T*BSZ*SEQ */
#define BSROWS    1024            /* BSZ*SEQ */

#define KTILE     64              /* fp16 K-elements per tile: 128B rows */
#define BUF_BYTES 32768           /* A 16KB + B 16KB */
#define DYN_SMEM  (2 * BUF_BYTES) /* 64 KB -> 2 CTAs/SM = 128 KB */

// ---------------- scratch (device globals; no allocation allowed) ----------
__device__ __half g_X  [(size_t)MROWS * HIDDEN];
__device__ __half g_WGU[(size_t)NFUSED * HIDDEN];   /* rows 0..5631 gate, 5632.. up */
__device__ __half g_WD [(size_t)HIDDEN * INTER_PAD];
__device__ __half g_GU [(size_t)MROWS * NFUSED];    /* fused gate/up outputs, fp16 */
__device__ __half g_C  [(size_t)MROWS * INTER_PAD]; /* combine output, fp16 */

// ---------------- helpers ----------------------------------------------------
__device__ __forceinline__ uint32_t smem_u32(const void* p) {
    uint32_t a;
    asm("{ .reg .u64 t; cvta.to.shared.u64 t, %1; cvt.u32.u64 %0, t; }" : "=r"(a) : "l"(p));
    return a;
}

#define LDSM_X4(r0, r1, r2, r3, addr) \
    asm volatile("ldmatrix.sync.aligned.m8n8.x4.shared.b16 {%0,%1,%2,%3}, [%4];" \
                 : "=r"(r0), "=r"(r1), "=r"(r2), "=r"(r3) : "r"(addr))

__device__ __forceinline__ void mma_f16(float* d, const uint32_t* a, const uint32_t* b) {
    asm volatile(
        "mma.sync.aligned.m16n8k16.row.col.f32.f16.f16.f32 "
        "{%0,%1,%2,%3}, {%4,%5,%6,%7}, {%8,%9}, {%0,%1,%2,%3};\n"
        : "+f"(d[0]), "+f"(d[1]), "+f"(d[2]), "+f"(d[3])
        : "r"(a[0]), "r"(a[1]), "r"(a[2]), "r"(a[3]), "r"(b[0]), "r"(b[1]));
}

// ---------------- GEMM: C[m,n] = sum_k A[m,k]*B[n,k] ------------------------
// Block tile 128x128, 128 threads, 4 warps (2x2), warp tile 64x64 (unchanged
// from the verified R15 inner loop). 2 CTAs/SM so one CTA's memory phase
// overlaps the other CTA's MMA phase (barrier convoy mitigation).
// Register-prefetched globals, double-buffered smem, one barrier per K-tile,
// bursty LDSM fragment loads (R15 order), m16n8k16 fp16 MMA, fp32 accumulate.
// OutT = __half or float. M%128==0, N%128==0, K%64==0.
template <typename OutT>
__global__ void __launch_bounds__(128, 2)
gemm_tn(const __half* __restrict__ A, const __half* __restrict__ B,
        OutT* __restrict__ C, int K, int N)
{
    extern __shared__ __align__(16) uint8_t smraw[];
    uint4* sm = reinterpret_cast<uint4*>(smraw);
    const uint32_t sb = smem_u32(smraw);

    const int tid  = threadIdx.x;
    const int lane = tid & 31;
    const int warp = tid >> 5;
    const int wm   = warp & 1;   // 2 warp rows of 64
    const int wn   = warp >> 1;  // 2 warp cols of 64

    const int r = tid >> 3;      // 0..15 : row within group of 16 (ldg/sts map)
    const int c = tid & 7;       // 0..7  : 16B (k8) atom within 128B row

    // LDSM per-lane selectors (verified bit-exact since R4):
    const int rsel   = lane & 7;
    const int a_k8hi = lane >> 4;
    const int a_moff = ((lane >> 3) & 1) << 3;
    const int b_k8lo = (lane >> 3) & 1;
    const int b_noff = (lane >> 4) << 3;
    const int mrowA  = wm * 64 + a_moff + rsel;
    const int nrowB  = wn * 64 + b_noff + rsel;

    const size_t mBase = (size_t)blockIdx.y * 128;
    const size_t nBase = (size_t)blockIdx.x * 128;
    const int NK = K / KTILE;

    const __half* Ag = A + (mBase + (size_t)r) * (size_t)K + (size_t)c * 8;
    const __half* Bg = B + (nBase + (size_t)r) * (size_t)K + (size_t)c * 8;

    uint4 pa[8], pb[8];

    auto ldg_tile = [&](int kt) {
        const __half* Ak = Ag + (size_t)kt * KTILE;
        const __half* Bk = Bg + (size_t)kt * KTILE;
        #pragma unroll
        for (int j = 0; j < 8; ++j) {
            pa[j] = *(const uint4*)(Ak + (size_t)(j * 16) * K);
            pb[j] = *(const uint4*)(Bk + (size_t)(j * 16) * K);
        }
    };
    // smem buffer: A atoms [k8(0..7)][m(0..127)] uint4 at slot m^k8;
    //              B atoms [k8(0..7)][n(0..127)] uint4 at slot n^k8 (at +16KB).
    auto sts_tile = [&](int buf) {
        uint4* As = sm + buf * (BUF_BYTES / 16);
        uint4* Bs = As + 1024;
        #pragma unroll
        for (int j = 0; j < 8; ++j) {
            const int m = j * 16 + r;
            const int slot = c * 128 + (m ^ c);
            As[slot] = pa[j];
            Bs[slot] = pb[j];
        }
    };

    float acc[4][8][4];
    #pragma unroll
    for (int i = 0; i < 4; ++i)
        #pragma unroll
        for (int j = 0; j < 8; ++j)
            #pragma unroll
            for (int q = 0; q < 4; ++q) acc[i][j][q] = 0.f;

    // prologue
    ldg_tile(0);
    sts_tile(0);
    if (NK > 1) ldg_tile(1);
    __syncthreads();

    for (int kt = 0; kt < NK; ++kt) {
        if (kt + 1 < NK) {
            sts_tile((kt + 1) & 1);
            if (kt + 2 < NK) ldg_tile(kt + 2);
        }

        const uint32_t abase = sb + (uint32_t)((kt & 1) * BUF_BYTES);
        const uint32_t bbase = abase + 16384;

        #pragma unroll
        for (int ks = 0; ks < 4; ++ks) {        // 4 k16-steps over 64-K tile
            const uint32_t ak8 = (uint32_t)(ks * 2 + a_k8hi);
            const uint32_t bk8 = (uint32_t)(ks * 2 + b_k8lo);

            uint32_t af[4][4];
            #pragma unroll
            for (int im = 0; im < 4; ++im) {
                const uint32_t m = (uint32_t)(mrowA + im * 16);
                const uint32_t addr = abase + (ak8 << 11) + (((m ^ ak8) & 127u) << 4);
                LDSM_X4(af[im][0], af[im][1], af[im][2], af[im][3], addr);
            }
            uint32_t bf[8][2];
            #pragma unroll
            for (int p = 0; p < 4; ++p) {
                const uint32_t n = (uint32_t)(nrowB + p * 16);
                const uint32_t addr = bbase + (bk8 << 11) + (((n ^ bk8) & 127u) << 4);
                LDSM_X4(bf[2 * p][0], bf[2 * p][1], bf[2 * p + 1][0], bf[2 * p + 1][1], addr);
            }
            #pragma unroll
            for (int im = 0; im < 4; ++im)
                #pragma unroll
                for (int jn = 0; jn < 8; ++jn)
                    mma_f16(acc[im][jn], af[im], bf[jn]);
        }
        __syncthreads();
    }

    // Epilogue: fragment layout -> global (pair of cols per quad-lane).
    const int g  = lane >> 2;
    const int q2 = (lane & 3) * 2;
    #pragma unroll
    for (int im = 0; im < 4; ++im) {
        const size_t row0 = mBase + wm * 64 + im * 16 + g;
        #pragma unroll
        for (int jn = 0; jn < 8; ++jn) {
            const size_t col0 = nBase + wn * 64 + jn * 8 + q2;
            if constexpr (sizeof(OutT) == 4) {
                *(float2*)&C[row0 * (size_t)N + col0] =
                    make_float2(acc[im][jn][0], acc[im][jn][1]);
                *(float2*)&C[(row0 + 8) * (size_t)N + col0] =
                    make_float2(acc[im][jn][2], acc[im][jn][3]);
            } else {
                *(__half2*)&C[row0 * (size_t)N + col0] =
                    __floats2half2_rn(acc[im][jn][0], acc[im][jn][1]);
                *(__half2*)&C[(row0 + 8) * (size_t)N + col0] =
                    __floats2half2_rn(acc[im][jn][2], acc[im][jn][3]);
            }
        }
    }
}

// ---------------- fused prepass (one launch) --------------------------------
__device__ __forceinline__ void store_h4(__half* dst, float4 v) {
    __half2* d2 = reinterpret_cast<__half2*>(dst);
    d2[0] = __floats2half2_rn(v.x, v.y);
    d2[1] = __floats2half2_rn(v.z, v.w);
}

#define PREP_S1 ((long)MROWS * HIDDEN / 4)               /* x copy          */
#define PREP_S2 (PREP_S1 + (long)INTER_PAD * HIDDEN / 4) /* gate (pad rows) */
#define PREP_S3 (PREP_S2 + (long)INTER_PAD * HIDDEN / 4) /* up   (pad rows) */
#define PREP_S4 (PREP_S3 + (long)HIDDEN * INTER_PAD / 4) /* w_down pad cols */

__global__ void prep_k(const float* __restrict__ x,
                       const float* __restrict__ wg, const float* __restrict__ wu,
                       const float* __restrict__ wd,
                       __half* __restrict__ dX, __half* __restrict__ dWGU,
                       __half* __restrict__ dWD)
{
    long i = (long)blockIdx.x * blockDim.x + threadIdx.x;
    if (i < PREP_S1) {
        long e = i * 4;
        store_h4(dX + e, *(const float4*)(x + e));
    } else if (i < PREP_S3) {
        const bool isUp = (i >= PREP_S2);
        long e = (i - (isUp ? PREP_S2 : PREP_S1)) * 4;
        int row = (int)(e / HIDDEN);
        float4 v = make_float4(0.f, 0.f, 0.f, 0.f);
        if (row < INTER) {
            const float* src = isUp ? wu : wg;
            v = *(const float4*)(src + (size_t)row * HIDDEN + (e % HIDDEN));
        }
        store_h4(dWGU + (isUp ? (size_t)INTER_PAD * HIDDEN : 0) + e, v);
    } else if (i < PREP_S4) {
        long e = (i - PREP_S3) * 4;
        int row = (int)(e / INTER_PAD);
        int col = (int)(e % INTER_PAD);
        float4 v = make_float4(0.f, 0.f, 0.f, 0.f);
        if (col < INTER)
            v = *(const float4*)(wd + (size_t)row * INTER + col);
        store_h4(dWD + e, v);
    }
}

// ---------------- combine: vectorized (8 cols per thread) -------------------
#define CCOL8 (INTER_PAD / 8)   /* 704 uint4 chunks per row */

__device__ __forceinline__ void h8_to_f(const uint4 q, float* f) {
    const __half2* h2 = reinterpret_cast<const __half2*>(&q);
    #pragma unroll
    for (int j = 0; j < 4; ++j) {
        float2 v = __half22float2(h2[j]);
        f[2 * j] = v.x; f[2 * j + 1] = v.y;
    }
}

__global__ void combine_k()
{
    const long total8 = (long)BSROWS * CCOL8;
    long idx = (long)blockIdx.x * blockDim.x + threadIdx.x;
    if (idx >= total8) return;

    const int row  = (int)(idx / CCOL8);
    const int col  = (int)(idx % CCOL8) * 8;
    const size_t rstride = (size_t)BSROWS * NFUSED;     // t-slab stride in GU
    const size_t cstride = (size_t)BSROWS * INTER_PAD;  // t-slab stride in C

    float gv[TSTEPS][8], uv[TSTEPS][8];
    #pragma unroll
    for (int t = 0; t < TSTEPS; ++t) {
        const __half* base = g_GU + (size_t)t * rstride + (size_t)row * NFUSED;
        h8_to_f(*(const uint4*)(base + col),             gv[t]);
        h8_to_f(*(const uint4*)(base + INTER_PAD + col), uv[t]);
    }

    float outv[TSTEPS][8];
    #pragma unroll
    for (int j = 0; j < 8; ++j) {
        float X = 0.f, Yprev = 0.f, SB = 0.f;
        float Av[TSTEPS];
        #pragma unroll
        for (int t = 0; t < TSTEPS; ++t) {
            X += gv[t][j];
            const float Y = X / (1.f + expf(-X));   // silu of cumsum
            Av[t] = Y - Yprev;
            Yprev = Y;
            SB += uv[t][j];
        }
        const float SA = Yprev;                     // telescoping sum of A
        #pragma unroll
        for (int t = 0; t < TSTEPS; ++t)
            outv[t][j] = 0.5f * (Av[t] * SB + uv[t][j] * SA);
    }

    #pragma unroll
    for (int t = 0; t < TSTEPS; ++t) {
        uint4 q;
        __half2* h2 = reinterpret_cast<__half2*>(&q);
        #pragma unroll
        for (int j = 0; j < 4; ++j)
            h2[j] = __floats2half2_rn(outv[t][2 * j], outv[t][2 * j + 1]);
        *(uint4*)(g_C + (size_t)t * cstride + (size_t)row * INTER_PAD + col) = q;
    }
}

// ---------------- launch -----------------------------------------------------
extern "C" void kernel_launch(void* const* d_in, const int* in_sizes, int n_in,
                              void* d_out, int out_size)
{
    const float* x      = (const float*)d_in[0];
    const float* w_gate = (const float*)d_in[1];
    const float* w_up   = (const float*)d_in[2];
    const float* w_down = (const float*)d_in[3];
    float* out = (float*)d_out;
    (void)in_sizes; (void)n_in; (void)out_size;

    __half *dX, *dWGU, *dWD, *dGU, *dC;
    cudaGetSymbolAddress((void**)&dX,   g_X);
    cudaGetSymbolAddress((void**)&dWGU, g_WGU);
    cudaGetSymbolAddress((void**)&dWD,  g_WD);
    cudaGetSymbolAddress((void**)&dGU,  g_GU);
    cudaGetSymbolAddress((void**)&dC,   g_C);

    cudaFuncSetAttribute(gemm_tn<__half>, cudaFuncAttributeMaxDynamicSharedMemorySize, DYN_SMEM);
    cudaFuncSetAttribute(gemm_tn<float>,  cudaFuncAttributeMaxDynamicSharedMemorySize, DYN_SMEM);

    // Fused prepass (one launch): fp32 -> fp16, weight pad/concat.
    prep_k<<<(unsigned)((PREP_S4 + 255) / 256), 256>>>(x, w_gate, w_up, w_down,
                                                       dX, dWGU, dWD);

    // Fused gate+up projection: (4096 x 11264) = x(4096x2048) @ [WG;WU]^T -> fp16
    {
        dim3 grid(NFUSED / 128, MROWS / 128);      // 88 x 32
        gemm_tn<__half><<<grid, 128, DYN_SMEM>>>(dX, dWGU, dGU, HIDDEN, NFUSED);
    }

    // Combine (vectorized: 8 cols/thread, fp32 math, fp16 out).
    {
        long total8 = (long)BSROWS * CCOL8;
        combine_k<<<(unsigned)((total8 + 255) / 256), 256>>>();
    }

    // Down projection: (4096 x 2048) = C(4096x5632) @ w_down'^T -> fp32 out
    {
        dim3 grid(HIDDEN / 128, MROWS / 128);      // 16 x 32
        gemm_tn<float><<<grid, 128, DYN_SMEM>>>(dC, dWD, out, INTER_PAD, HIDDEN);
    }
}